// round 5
// baseline (speedup 1.0000x reference)
#include <cuda_runtime.h>
#include <math.h>

// Problem constants
#define T_TOK 8192
#define HD    1024
#define ID    2816
#define NE    8
#define NS    16384          // T_TOK * top_k (always exact: every token picks 2)
#define RB    1024           // router blocks (8 tokens each)

// GEMM tiling
#define BM 128
#define BN 128
#define BKT 16
#define GP 4
#define ASTRIDE (BKT+GP)     // 20
#define BSTRIDE (BN+GP)      // 132

// ---------------- scratch (device globals; no allocation allowed) ----------------
__device__ float g_Hg[(size_t)NS*ID];     // gate raw, then silu(gate)*up (in place)
__device__ float g_Y [(size_t)NS*HD];     // down-proj per-slot output
__device__ float g_topw[T_TOK*2];
__device__ int   g_topidx[T_TOK*2];
__device__ int   g_slot[T_TOK*2];
__device__ int   g_tok[NS];
__device__ int   g_cnt[NE];
__device__ int   g_off[NE];
__device__ int   g_fill[NE];
__device__ float g_probpart[RB*NE];

// ---------------- helpers ----------------
__device__ __forceinline__ unsigned f2tf(float x){
    unsigned r; asm("cvt.rna.tf32.f32 %0, %1;" : "=r"(r) : "f"(x)); return r;
}
__device__ __forceinline__ float4 cvt4(float4 v){
    float4 o;
    o.x = __uint_as_float(f2tf(v.x));
    o.y = __uint_as_float(f2tf(v.y));
    o.z = __uint_as_float(f2tf(v.z));
    o.w = __uint_as_float(f2tf(v.w));
    return o;
}
__device__ __forceinline__ void mma8(float* d, const unsigned* a, const unsigned* b){
    asm volatile(
        "mma.sync.aligned.m16n8k8.row.col.f32.tf32.tf32.f32 "
        "{%0,%1,%2,%3}, {%4,%5,%6,%7}, {%8,%9}, {%0,%1,%2,%3};\n"
        : "+f"(d[0]), "+f"(d[1]), "+f"(d[2]), "+f"(d[3])
        : "r"(a[0]), "r"(a[1]), "r"(a[2]), "r"(a[3]), "r"(b[0]), "r"(b[1]));
}

// ---------------- K0: init counters ----------------
__global__ void k_init(){
    int i = threadIdx.x;
    if (i < NE){ g_cnt[i] = 0; g_fill[i] = 0; }
}

// ---------------- K1: router (1 warp per token) ----------------
__global__ __launch_bounds__(256) void k_router(const float* __restrict__ x,
                                                const float* __restrict__ Wr){
    __shared__ float sp[8][8];     // [warp][expert] probs of this block's tokens
    __shared__ int   shc[8];
    int tid = threadIdx.x, wid = tid >> 5, lane = tid & 31;
    if (tid < 8) shc[tid] = 0;
    __syncthreads();

    int t = blockIdx.x * 8 + wid;
    const float* xr = x + (size_t)t * HD;
    float acc[8];
    #pragma unroll
    for (int e = 0; e < 8; e++) acc[e] = 0.f;

    for (int h0 = 0; h0 < HD; h0 += 32){
        float xv = xr[h0 + lane];
        const float4* w = (const float4*)(Wr + (size_t)(h0 + lane) * NE);
        float4 w0 = w[0], w1 = w[1];
        acc[0] += xv*w0.x; acc[1] += xv*w0.y; acc[2] += xv*w0.z; acc[3] += xv*w0.w;
        acc[4] += xv*w1.x; acc[5] += xv*w1.y; acc[6] += xv*w1.z; acc[7] += xv*w1.w;
    }
    #pragma unroll
    for (int e = 0; e < 8; e++)
        #pragma unroll
        for (int o = 16; o > 0; o >>= 1)
            acc[e] += __shfl_xor_sync(0xffffffffu, acc[e], o);

    if (lane == 0){
        float mx = acc[0];
        #pragma unroll
        for (int e = 1; e < 8; e++) mx = fmaxf(mx, acc[e]);
        float p[8], s = 0.f;
        #pragma unroll
        for (int e = 0; e < 8; e++){ p[e] = expf(acc[e] - mx); s += p[e]; }
        float inv = 1.f / s;
        #pragma unroll
        for (int e = 0; e < 8; e++){ p[e] *= inv; sp[wid][e] = p[e]; }
        int i0 = 0; float v0 = p[0];
        #pragma unroll
        for (int e = 1; e < 8; e++) if (p[e] > v0){ v0 = p[e]; i0 = e; }
        int i1 = -1; float v1 = -1.f;
        #pragma unroll
        for (int e = 0; e < 8; e++) if (e != i0 && p[e] > v1){ v1 = p[e]; i1 = e; }
        float rs = 1.f / (v0 + v1 + 1e-9f);
        g_topw[2*t]   = v0 * rs;  g_topw[2*t+1]   = v1 * rs;
        g_topidx[2*t] = i0;       g_topidx[2*t+1] = i1;
        atomicAdd(&shc[i0], 1);   atomicAdd(&shc[i1], 1);
    }
    __syncthreads();
    if (tid < 8){
        float s = 0.f;
        #pragma unroll
        for (int w = 0; w < 8; w++) s += sp[w][tid];
        g_probpart[blockIdx.x * 8 + tid] = s;
        atomicAdd(&g_cnt[tid], shc[tid]);
    }
}

// ---------------- K2: offsets + deterministic aux loss ----------------
__global__ void k_finalize(float* __restrict__ out, int out_size){
    __shared__ float sp2[32][8];
    __shared__ float pm[8];
    int tid = threadIdx.x;
    int e = tid & 7, ch = tid >> 3;          // 256 threads: 32 chunks x 8 experts
    float s = 0.f;
    for (int j = ch * 32; j < ch * 32 + 32; j++) s += g_probpart[j * 8 + e];
    sp2[ch][e] = s;
    __syncthreads();
    if (tid < 8){
        float ss = 0.f;
        for (int c = 0; c < 32; c++) ss += sp2[c][tid];
        pm[tid] = ss / (float)T_TOK;
        g_fill[tid] = 0;
    }
    __syncthreads();
    if (tid == 0){
        int o = 0;
        for (int i = 0; i < NE; i++){ g_off[i] = o; o += g_cnt[i]; }
        float loss = 0.f;
        for (int i = 0; i < NE; i++) loss += pm[i] * ((float)g_cnt[i] / (float)T_TOK);
        loss *= (float)NE * 0.01f;
        if (out_size > T_TOK * HD) out[T_TOK * HD] = loss;
    }
}

// ---------------- K3: slot assignment (block-aggregated atomics) ----------------
// Slot ordering within an expert is nondeterministic across replays, but every
// slot's VALUE depends only on its own token row, and combine reads via g_slot,
// so the final output is replay-invariant.
__global__ void k_assign(){
    __shared__ int shc[8], shbase[8];
    int tid = threadIdx.x;
    int t = blockIdx.x * 256 + tid;
    if (tid < 8) shc[tid] = 0;
    __syncthreads();
    int e0 = g_topidx[2*t], e1 = g_topidx[2*t+1];
    int p0 = atomicAdd(&shc[e0], 1);
    int p1 = atomicAdd(&shc[e1], 1);
    __syncthreads();
    if (tid < 8) shbase[tid] = atomicAdd(&g_fill[tid], shc[tid]);
    __syncthreads();
    int s0 = g_off[e0] + shbase[e0] + p0;
    int s1 = g_off[e1] + shbase[e1] + p1;
    g_slot[2*t] = s0;  g_slot[2*t+1] = s1;
    g_tok[s0] = t;     g_tok[s1] = t;
}

// ---------------- K4: tiled TF32 GEMM (3 modes) ----------------
// MODE 0: Hg_raw = Xg @ Wg_e                    (A = gathered x rows)
// MODE 1: Hg     = silu(Hg_raw) * (Xg @ Wu_e)   (in-place epilogue)
// MODE 2: Y      = Hg @ Wd_e                    (A = contiguous Hg rows)
template<int MODE>
__global__ __launch_bounds__(256, 1) void k_gemm(const float* __restrict__ Abase,
                                                 const float* __restrict__ W,
                                                 int Kdim, int Ndim){
    __shared__ float As[2][BM][ASTRIDE];
    __shared__ float Bs[2][BKT][BSTRIDE];

    int e = blockIdx.z;
    int cnt = g_cnt[e], off = g_off[e];
    int row0 = blockIdx.x * BM;
    if (row0 >= cnt) return;
    int n0 = blockIdx.y * BN;
    const float* Wp = W + (size_t)e * Kdim * Ndim;

    int tid = threadIdx.x, lane = tid & 31, wid = tid >> 5;
    int wm = wid & 3, wn = wid >> 2;           // 4x2 warps, warp tile 32x64
    int gq = lane >> 2, qq = lane & 3;

    // A loader: rows mA0 = tid/4 and mA0+64, cols kqA..kqA+3
    int mA0 = tid >> 2, kqA = (tid & 3) * 4;
    const float* arow0; const float* arow1;
    if (MODE <= 1){
        int r0 = row0 + mA0, r1 = row0 + mA0 + 64;
        int t0 = (r0 < cnt) ? g_tok[off + r0] : 0;
        int t1 = (r1 < cnt) ? g_tok[off + r1] : 0;
        arow0 = Abase + (size_t)t0 * Kdim;
        arow1 = Abase + (size_t)t1 * Kdim;
    } else {
        int s0 = off + row0 + mA0;      if (s0 >= NS) s0 = NS - 1;
        int s1 = off + row0 + mA0 + 64; if (s1 >= NS) s1 = NS - 1;
        arow0 = g_Hg + (size_t)s0 * Kdim;
        arow1 = g_Hg + (size_t)s1 * Kdim;
    }
    // B loader: rows kB and kB+8, cols nB4..nB4+3
    int kB = tid >> 5, nB4 = (tid & 31) * 4;
    const float* bptr = Wp + (size_t)kB * Ndim + n0 + nB4;

    float acc[2][8][4];
    #pragma unroll
    for (int mt = 0; mt < 2; mt++)
        #pragma unroll
        for (int nt = 0; nt < 8; nt++)
            #pragma unroll
            for (int i = 0; i < 4; i++) acc[mt][nt][i] = 0.f;

    int KT = Kdim / BKT;

    // prologue: tile 0 -> buf 0
    {
        float4 a0 = *(const float4*)(arow0 + kqA);
        float4 a1 = *(const float4*)(arow1 + kqA);
        float4 b0 = *(const float4*)(bptr);
        float4 b1 = *(const float4*)(bptr + (size_t)8 * Ndim);
        *(float4*)(&As[0][mA0   ][kqA]) = cvt4(a0);
        *(float4*)(&As[0][mA0+64][kqA]) = cvt4(a1);
        *(float4*)(&Bs[0][kB  ][nB4]) = cvt4(b0);
        *(float4*)(&Bs[0][kB+8][nB4]) = cvt4(b1);
    }
    __syncthreads();

    for (int kt = 0; kt < KT; kt++){
        int cb = kt & 1;
        bool pf = (kt + 1 < KT);
        float4 a0n, a1n, b0n, b1n;
        if (pf){
            int koff = (kt + 1) * BKT;
            a0n = *(const float4*)(arow0 + koff + kqA);
            a1n = *(const float4*)(arow1 + koff + kqA);
            b0n = *(const float4*)(bptr + (size_t)koff * Ndim);
            b1n = *(const float4*)(bptr + (size_t)(koff + 8) * Ndim);
        }
        #pragma unroll
        for (int ks = 0; ks < 2; ks++){
            int k0 = ks * 8;
            unsigned af[2][4];
            #pragma unroll
            for (int mt = 0; mt < 2; mt++){
                int r = wm * 32 + mt * 16 + gq;
                af[mt][0] = __float_as_uint(As[cb][r    ][k0 + qq    ]);
                af[mt][1] = __float_as_uint(As[cb][r + 8][k0 + qq    ]);
                af[mt][2] = __float_as_uint(As[cb][r    ][k0 + qq + 4]);
                af[mt][3] = __float_as_uint(As[cb][r + 8][k0 + qq + 4]);
            }
            unsigned bf[8][2];
            #pragma unroll
            for (int nt = 0; nt < 8; nt++){
                int c = wn * 64 + nt * 8 + gq;
                bf[nt][0] = __float_as_uint(Bs[cb][k0 + qq    ][c]);
                bf[nt][1] = __float_as_uint(Bs[cb][k0 + qq + 4][c]);
            }
            #pragma unroll
            for (int mt = 0; mt < 2; mt++)
                #pragma unroll
                for (int nt = 0; nt < 8; nt++)
                    mma8(acc[mt][nt], af[mt], bf[nt]);
        }
        if (pf){
            int nb = (kt + 1) & 1;
            *(float4*)(&As[nb][mA0   ][kqA]) = cvt4(a0n);
            *(float4*)(&As[nb][mA0+64][kqA]) = cvt4(a1n);
            *(float4*)(&Bs[nb][kB  ][nB4]) = cvt4(b0n);
            *(float4*)(&Bs[nb][kB+8][nB4]) = cvt4(b1n);
        }
        __syncthreads();
    }

    // epilogue
    int valid = cnt - row0;
    #pragma unroll
    for (int mt = 0; mt < 2; mt++){
        int rbase = wm * 32 + mt * 16 + gq;
        #pragma unroll
        for (int half = 0; half < 2; half++){
            int m = rbase + half * 8;
            if (m < valid){
                size_t slot = (size_t)(off + row0 + m);
                #pragma unroll
                for (int nt = 0; nt < 8; nt++){
                    int c = n0 + wn * 64 + nt * 8 + qq * 2;
                    float v0 = acc[mt][nt][half * 2 + 0];
                    float v1 = acc[mt][nt][half * 2 + 1];
                    if (MODE == 0){
                        *(float2*)&g_Hg[slot * ID + c] = make_float2(v0, v1);
                    } else if (MODE == 1){
                        float2* p = (float2*)&g_Hg[slot * ID + c];
                        float2 gt = *p;
                        float h0 = gt.x / (1.f + expf(-gt.x)) * v0;
                        float h1 = gt.y / (1.f + expf(-gt.y)) * v1;
                        *p = make_float2(h0, h1);
                    } else {
                        *(float2*)&g_Y[slot * HD + c] = make_float2(v0, v1);
                    }
                }
            }
        }
    }
}

// ---------------- K5: weighted combine ----------------
__global__ void k_combine(float* __restrict__ out){
    int t = blockIdx.x;
    float w0 = g_topw[2*t], w1 = g_topw[2*t+1];
    const float4* y0 = (const float4*)(g_Y + (size_t)g_slot[2*t]   * HD);
    const float4* y1 = (const float4*)(g_Y + (size_t)g_slot[2*t+1] * HD);
    float4* o = (float4*)(out + (size_t)t * HD);
    int i = threadIdx.x;                      // 256 threads, HD/4 = 256
    float4 a = y0[i], b = y1[i];
    o[i] = make_float4(w0*a.x + w1*b.x, w0*a.y + w1*b.y,
                       w0*a.z + w1*b.z, w0*a.w + w1*b.w);
}

// ---------------- launch ----------------
extern "C" void kernel_launch(void* const* d_in, const int* in_sizes, int n_in,
                              void* d_out, int out_size){
    const float* x  = (const float*)d_in[0];   // [8192, 1024]
    const float* Wr = (const float*)d_in[1];   // [1024, 8]
    const float* Wg = (const float*)d_in[2];   // [8, 1024, 2816]
    const float* Wu = (const float*)d_in[3];   // [8, 1024, 2816]
    const float* Wd = (const float*)d_in[4];   // [8, 2816, 1024]
    float* out = (float*)d_out;

    k_init<<<1, 32>>>();
    k_router<<<RB, 256>>>(x, Wr);
    k_finalize<<<1, 256>>>(out, out_size);
    k_assign<<<T_TOK / 256, 256>>>();

    dim3 g1(T_TOK / BM, ID / BN, NE);          // (64, 22, 8)
    k_gemm<0><<<g1, 256>>>(x, Wg, HD, ID);
    k_gemm<1><<<g1, 256>>>(x, Wu, HD, ID);
    dim3 g3(T_TOK / BM, HD / BN, NE);          // (64, 8, 8)
    k_gemm<2><<<g3, 256>>>(x, Wd, ID, HD);

    k_combine<<<T_TOK, 256>>>(out);
}

// round 8
// speedup vs baseline: 1.7419x; 1.7419x over previous
#include <cuda_runtime.h>
#include <math.h>
#include <stdint.h>

// Problem constants
#define T_TOK 8192
#define HD    1024
#define ID    2816
#define NE    8
#define NS    16384          // T_TOK * top_k
#define RB    1024

// GEMM tiling
#define BM 128
#define BN 128
#define BKT 16
#define ASTRIDE 20           // BKT+4
#define BSTRIDE 136          // BN+8 -> mod 32 == 8: conflict-free fragment loads

// ---------------- scratch ----------------
__device__ float g_Hg[(size_t)NS*ID];     // silu(gate)*up
__device__ float g_Y [(size_t)NS*HD];     // down output
__device__ float g_topw[T_TOK*2];
__device__ int   g_topidx[T_TOK*2];
__device__ int   g_slot[T_TOK*2];
__device__ int   g_tok[NS];
__device__ int   g_cnt[NE];
__device__ int   g_off[NE];
__device__ int   g_fill[NE];
__device__ float g_probpart[RB*NE];

// ---------------- helpers ----------------
__device__ __forceinline__ unsigned f2tf(float x){
    unsigned r; asm("cvt.rna.tf32.f32 %0, %1;" : "=r"(r) : "f"(x)); return r;
}
__device__ __forceinline__ float4 cvt4(float4 v){
    float4 o;
    o.x = __uint_as_float(f2tf(v.x));
    o.y = __uint_as_float(f2tf(v.y));
    o.z = __uint_as_float(f2tf(v.z));
    o.w = __uint_as_float(f2tf(v.w));
    return o;
}
__device__ __forceinline__ void mma8(float* d, const unsigned* a, const unsigned* b){
    asm volatile(
        "mma.sync.aligned.m16n8k8.row.col.f32.tf32.tf32.f32 "
        "{%0,%1,%2,%3}, {%4,%5,%6,%7}, {%8,%9}, {%0,%1,%2,%3};\n"
        : "+f"(d[0]), "+f"(d[1]), "+f"(d[2]), "+f"(d[3])
        : "r"(a[0]), "r"(a[1]), "r"(a[2]), "r"(a[3]), "r"(b[0]), "r"(b[1]));
}

// ---------------- K0: init ----------------
__global__ void k_init(){
    int i = threadIdx.x;
    if (i < NE){ g_cnt[i] = 0; g_fill[i] = 0; }
}

// ---------------- K1: router ----------------
__global__ __launch_bounds__(256) void k_router(const float* __restrict__ x,
                                                const float* __restrict__ Wr){
    __shared__ float sp[8][8];
    __shared__ int   shc[8];
    int tid = threadIdx.x, wid = tid >> 5, lane = tid & 31;
    if (tid < 8) shc[tid] = 0;
    __syncthreads();

    int t = blockIdx.x * 8 + wid;
    const float* xr = x + (size_t)t * HD;
    float acc[8];
    #pragma unroll
    for (int e = 0; e < 8; e++) acc[e] = 0.f;

    for (int h0 = 0; h0 < HD; h0 += 32){
        float xv = xr[h0 + lane];
        const float4* w = (const float4*)(Wr + (size_t)(h0 + lane) * NE);
        float4 w0 = w[0], w1 = w[1];
        acc[0] += xv*w0.x; acc[1] += xv*w0.y; acc[2] += xv*w0.z; acc[3] += xv*w0.w;
        acc[4] += xv*w1.x; acc[5] += xv*w1.y; acc[6] += xv*w1.z; acc[7] += xv*w1.w;
    }
    #pragma unroll
    for (int e = 0; e < 8; e++)
        #pragma unroll
        for (int o = 16; o > 0; o >>= 1)
            acc[e] += __shfl_xor_sync(0xffffffffu, acc[e], o);

    if (lane == 0){
        float mx = acc[0];
        #pragma unroll
        for (int e = 1; e < 8; e++) mx = fmaxf(mx, acc[e]);
        float p[8], s = 0.f;
        #pragma unroll
        for (int e = 0; e < 8; e++){ p[e] = expf(acc[e] - mx); s += p[e]; }
        float inv = 1.f / s;
        #pragma unroll
        for (int e = 0; e < 8; e++){ p[e] *= inv; sp[wid][e] = p[e]; }
        int i0 = 0; float v0 = p[0];
        #pragma unroll
        for (int e = 1; e < 8; e++) if (p[e] > v0){ v0 = p[e]; i0 = e; }
        int i1 = -1; float v1 = -1.f;
        #pragma unroll
        for (int e = 0; e < 8; e++) if (e != i0 && p[e] > v1){ v1 = p[e]; i1 = e; }
        float rs = 1.f / (v0 + v1 + 1e-9f);
        g_topw[2*t]   = v0 * rs;  g_topw[2*t+1]   = v1 * rs;
        g_topidx[2*t] = i0;       g_topidx[2*t+1] = i1;
        atomicAdd(&shc[i0], 1);   atomicAdd(&shc[i1], 1);
    }
    __syncthreads();
    if (tid < 8){
        float s = 0.f;
        #pragma unroll
        for (int w = 0; w < 8; w++) s += sp[w][tid];
        g_probpart[blockIdx.x * 8 + tid] = s;
        atomicAdd(&g_cnt[tid], shc[tid]);
    }
}

// ---------------- K2: offsets + aux loss ----------------
__global__ void k_finalize(float* __restrict__ out, int out_size){
    __shared__ float sp2[32][8];
    __shared__ float pm[8];
    int tid = threadIdx.x;
    int e = tid & 7, ch = tid >> 3;
    float s = 0.f;
    for (int j = ch * 32; j < ch * 32 + 32; j++) s += g_probpart[j * 8 + e];
    sp2[ch][e] = s;
    __syncthreads();
    if (tid < 8){
        float ss = 0.f;
        for (int c = 0; c < 32; c++) ss += sp2[c][tid];
        pm[tid] = ss / (float)T_TOK;
        g_fill[tid] = 0;
    }
    __syncthreads();
    if (tid == 0){
        int o = 0;
        for (int i = 0; i < NE; i++){ g_off[i] = o; o += g_cnt[i]; }
        float loss = 0.f;
        for (int i = 0; i < NE; i++) loss += pm[i] * ((float)g_cnt[i] / (float)T_TOK);
        loss *= (float)NE * 0.01f;
        if (out_size > T_TOK * HD) out[T_TOK * HD] = loss;
    }
}

// ---------------- K3: slot assignment ----------------
__global__ void k_assign(){
    __shared__ int shc[8], shbase[8];
    int tid = threadIdx.x;
    int t = blockIdx.x * 256 + tid;
    if (tid < 8) shc[tid] = 0;
    __syncthreads();
    int e0 = g_topidx[2*t], e1 = g_topidx[2*t+1];
    int p0 = atomicAdd(&shc[e0], 1);
    int p1 = atomicAdd(&shc[e1], 1);
    __syncthreads();
    if (tid < 8) shbase[tid] = atomicAdd(&g_fill[tid], shc[tid]);
    __syncthreads();
    int s0 = g_off[e0] + shbase[e0] + p0;
    int s1 = g_off[e1] + shbase[e1] + p1;
    g_slot[2*t] = s0;  g_slot[2*t+1] = s1;
    g_tok[s0] = t;     g_tok[s1] = t;
}

// ---------------- K4: fused gate+up GEMM ----------------
// Hg[slot, n] = silu(Xg @ Wg_e)[.,n] * (Xg @ Wu_e)[.,n]
// One A tile feeds both B tiles. Dyn smem:
//   As [2][128][ASTRIDE]  5120 f
//   Bg [2][16][BSTRIDE]   4352 f
//   Bu [2][16][BSTRIDE]   4352 f      total 13824 f = 55296 B
#define GU_SMEM_FLOATS 13824
#define AS_OFF 0
#define BG_OFF 5120
#define BU_OFF 9472
__global__ __launch_bounds__(256, 1) void k_gateup(const float* __restrict__ x,
                                                   const float* __restrict__ Wg,
                                                   const float* __restrict__ Wu){
    extern __shared__ float smf[];
    float* As = smf + AS_OFF;   // [b][m][ASTRIDE] : b*2560 + m*20 + k
    float* Bg = smf + BG_OFF;   // [b][k][BSTRIDE] : b*2176 + k*136 + c
    float* Bu = smf + BU_OFF;

    int e = blockIdx.z;
    int cnt = g_cnt[e], off = g_off[e];
    int row0 = blockIdx.x * BM;
    if (row0 >= cnt) return;
    int n0 = blockIdx.y * BN;
    const float* Wgp = Wg + (size_t)e * HD * ID;
    const float* Wup = Wu + (size_t)e * HD * ID;

    int tid = threadIdx.x, lane = tid & 31, wid = tid >> 5;
    int wm = wid & 3, wn = wid >> 2;           // 4x2 warps, warp tile 32x64
    int gq = lane >> 2, qq = lane & 3;

    // A loader: rows mA0, mA0+64
    int mA0 = tid >> 2, kqA = (tid & 3) * 4;
    int r0 = row0 + mA0, r1 = row0 + mA0 + 64;
    int t0 = (r0 < cnt) ? g_tok[off + r0] : 0;
    int t1 = (r1 < cnt) ? g_tok[off + r1] : 0;
    const float* arow0 = x + (size_t)t0 * HD;
    const float* arow1 = x + (size_t)t1 * HD;
    // B loader: rows kB, kB+8, cols nB4..nB4+3
    int kB = tid >> 5, nB4 = (tid & 31) * 4;
    const float* bgp = Wgp + (size_t)kB * ID + n0 + nB4;
    const float* bup = Wup + (size_t)kB * ID + n0 + nB4;

    float accg[2][8][4], accu[2][8][4];
    #pragma unroll
    for (int mt = 0; mt < 2; mt++)
        #pragma unroll
        for (int nt = 0; nt < 8; nt++)
            #pragma unroll
            for (int i = 0; i < 4; i++){ accg[mt][nt][i] = 0.f; accu[mt][nt][i] = 0.f; }

    const int KT = HD / BKT;     // 64

    // prologue
    {
        *(float4*)(As + mA0*ASTRIDE + kqA)        = cvt4(*(const float4*)(arow0 + kqA));
        *(float4*)(As + (mA0+64)*ASTRIDE + kqA)   = cvt4(*(const float4*)(arow1 + kqA));
        *(float4*)(Bg + kB*BSTRIDE + nB4)         = cvt4(*(const float4*)(bgp));
        *(float4*)(Bg + (kB+8)*BSTRIDE + nB4)     = cvt4(*(const float4*)(bgp + (size_t)8*ID));
        *(float4*)(Bu + kB*BSTRIDE + nB4)         = cvt4(*(const float4*)(bup));
        *(float4*)(Bu + (kB+8)*BSTRIDE + nB4)     = cvt4(*(const float4*)(bup + (size_t)8*ID));
    }
    __syncthreads();

    for (int kt = 0; kt < KT; kt++){
        int cb = kt & 1;
        float* Asc = As + cb*2560;
        float* Bgc = Bg + cb*2176;
        float* Buc = Bu + cb*2176;
        bool pf = (kt + 1 < KT);
        float4 a0n, a1n, g0n, g1n, u0n, u1n;
        if (pf){
            int ko = (kt + 1) * BKT;
            a0n = *(const float4*)(arow0 + ko + kqA);
            a1n = *(const float4*)(arow1 + ko + kqA);
            g0n = *(const float4*)(bgp + (size_t)ko * ID);
            g1n = *(const float4*)(bgp + (size_t)(ko + 8) * ID);
            u0n = *(const float4*)(bup + (size_t)ko * ID);
            u1n = *(const float4*)(bup + (size_t)(ko + 8) * ID);
        }
        #pragma unroll
        for (int ks = 0; ks < 2; ks++){
            int k0 = ks * 8;
            unsigned af[2][4];
            #pragma unroll
            for (int mt = 0; mt < 2; mt++){
                int r = wm * 32 + mt * 16 + gq;
                af[mt][0] = __float_as_uint(Asc[(r    )*ASTRIDE + k0 + qq    ]);
                af[mt][1] = __float_as_uint(Asc[(r + 8)*ASTRIDE + k0 + qq    ]);
                af[mt][2] = __float_as_uint(Asc[(r    )*ASTRIDE + k0 + qq + 4]);
                af[mt][3] = __float_as_uint(Asc[(r + 8)*ASTRIDE + k0 + qq + 4]);
            }
            {
                unsigned bf[8][2];
                #pragma unroll
                for (int nt = 0; nt < 8; nt++){
                    int c = wn * 64 + nt * 8 + gq;
                    bf[nt][0] = __float_as_uint(Bgc[(k0 + qq    )*BSTRIDE + c]);
                    bf[nt][1] = __float_as_uint(Bgc[(k0 + qq + 4)*BSTRIDE + c]);
                }
                #pragma unroll
                for (int mt = 0; mt < 2; mt++)
                    #pragma unroll
                    for (int nt = 0; nt < 8; nt++)
                        mma8(accg[mt][nt], af[mt], bf[nt]);
            }
            {
                unsigned bf[8][2];
                #pragma unroll
                for (int nt = 0; nt < 8; nt++){
                    int c = wn * 64 + nt * 8 + gq;
                    bf[nt][0] = __float_as_uint(Buc[(k0 + qq    )*BSTRIDE + c]);
                    bf[nt][1] = __float_as_uint(Buc[(k0 + qq + 4)*BSTRIDE + c]);
                }
                #pragma unroll
                for (int mt = 0; mt < 2; mt++)
                    #pragma unroll
                    for (int nt = 0; nt < 8; nt++)
                        mma8(accu[mt][nt], af[mt], bf[nt]);
            }
        }
        if (pf){
            int nb = (kt + 1) & 1;
            float* Asn = As + nb*2560;
            float* Bgn = Bg + nb*2176;
            float* Bun = Bu + nb*2176;
            *(float4*)(Asn + mA0*ASTRIDE + kqA)      = cvt4(a0n);
            *(float4*)(Asn + (mA0+64)*ASTRIDE + kqA) = cvt4(a1n);
            *(float4*)(Bgn + kB*BSTRIDE + nB4)       = cvt4(g0n);
            *(float4*)(Bgn + (kB+8)*BSTRIDE + nB4)   = cvt4(g1n);
            *(float4*)(Bun + kB*BSTRIDE + nB4)       = cvt4(u0n);
            *(float4*)(Bun + (kB+8)*BSTRIDE + nB4)   = cvt4(u1n);
        }
        __syncthreads();
    }

    // epilogue: silu(g)*u -> g_Hg
    int valid = cnt - row0;
    #pragma unroll
    for (int mt = 0; mt < 2; mt++){
        int rbase = wm * 32 + mt * 16 + gq;
        #pragma unroll
        for (int half = 0; half < 2; half++){
            int m = rbase + half * 8;
            if (m < valid){
                size_t slot = (size_t)(off + row0 + m);
                #pragma unroll
                for (int nt = 0; nt < 8; nt++){
                    int c = n0 + wn * 64 + nt * 8 + qq * 2;
                    float gg0 = accg[mt][nt][half * 2 + 0];
                    float gg1 = accg[mt][nt][half * 2 + 1];
                    float uu0 = accu[mt][nt][half * 2 + 0];
                    float uu1 = accu[mt][nt][half * 2 + 1];
                    float h0 = gg0 / (1.f + expf(-gg0)) * uu0;
                    float h1 = gg1 / (1.f + expf(-gg1)) * uu1;
                    *(float2*)&g_Hg[slot * ID + c] = make_float2(h0, h1);
                }
            }
        }
    }
}

// ---------------- K5: down GEMM ----------------
__global__ __launch_bounds__(256, 1) void k_down(const float* __restrict__ Wd){
    __shared__ float As[2][BM][ASTRIDE];
    __shared__ float Bs[2][BKT][BSTRIDE];

    int e = blockIdx.z;
    int cnt = g_cnt[e], off = g_off[e];
    int row0 = blockIdx.x * BM;
    if (row0 >= cnt) return;
    int n0 = blockIdx.y * BN;
    const float* Wp = Wd + (size_t)e * ID * HD;

    int tid = threadIdx.x, lane = tid & 31, wid = tid >> 5;
    int wm = wid & 3, wn = wid >> 2;
    int gq = lane >> 2, qq = lane & 3;

    int mA0 = tid >> 2, kqA = (tid & 3) * 4;
    int s0 = off + row0 + mA0;      if (s0 >= NS) s0 = NS - 1;
    int s1 = off + row0 + mA0 + 64; if (s1 >= NS) s1 = NS - 1;
    const float* arow0 = g_Hg + (size_t)s0 * ID;
    const float* arow1 = g_Hg + (size_t)s1 * ID;

    int kB = tid >> 5, nB4 = (tid & 31) * 4;
    const float* bptr = Wp + (size_t)kB * HD + n0 + nB4;

    float acc[2][8][4];
    #pragma unroll
    for (int mt = 0; mt < 2; mt++)
        #pragma unroll
        for (int nt = 0; nt < 8; nt++)
            #pragma unroll
            for (int i = 0; i < 4; i++) acc[mt][nt][i] = 0.f;

    const int KT = ID / BKT;      // 176

    {
        *(float4*)(&As[0][mA0   ][kqA]) = cvt4(*(const float4*)(arow0 + kqA));
        *(float4*)(&As[0][mA0+64][kqA]) = cvt4(*(const float4*)(arow1 + kqA));
        *(float4*)(&Bs[0][kB  ][nB4])   = cvt4(*(const float4*)(bptr));
        *(float4*)(&Bs[0][kB+8][nB4])   = cvt4(*(const float4*)(bptr + (size_t)8 * HD));
    }
    __syncthreads();

    for (int kt = 0; kt < KT; kt++){
        int cb = kt & 1;
        bool pf = (kt + 1 < KT);
        float4 a0n, a1n, b0n, b1n;
        if (pf){
            int ko = (kt + 1) * BKT;
            a0n = *(const float4*)(arow0 + ko + kqA);
            a1n = *(const float4*)(arow1 + ko + kqA);
            b0n = *(const float4*)(bptr + (size_t)ko * HD);
            b1n = *(const float4*)(bptr + (size_t)(ko + 8) * HD);
        }
        #pragma unroll
        for (int ks = 0; ks < 2; ks++){
            int k0 = ks * 8;
            unsigned af[2][4];
            #pragma unroll
            for (int mt = 0; mt < 2; mt++){
                int r = wm * 32 + mt * 16 + gq;
                af[mt][0] = __float_as_uint(As[cb][r    ][k0 + qq    ]);
                af[mt][1] = __float_as_uint(As[cb][r + 8][k0 + qq    ]);
                af[mt][2] = __float_as_uint(As[cb][r    ][k0 + qq + 4]);
                af[mt][3] = __float_as_uint(As[cb][r + 8][k0 + qq + 4]);
            }
            unsigned bf[8][2];
            #pragma unroll
            for (int nt = 0; nt < 8; nt++){
                int c = wn * 64 + nt * 8 + gq;
                bf[nt][0] = __float_as_uint(Bs[cb][k0 + qq    ][c]);
                bf[nt][1] = __float_as_uint(Bs[cb][k0 + qq + 4][c]);
            }
            #pragma unroll
            for (int mt = 0; mt < 2; mt++)
                #pragma unroll
                for (int nt = 0; nt < 8; nt++)
                    mma8(acc[mt][nt], af[mt], bf[nt]);
        }
        if (pf){
            int nb = (kt + 1) & 1;
            *(float4*)(&As[nb][mA0   ][kqA]) = cvt4(a0n);
            *(float4*)(&As[nb][mA0+64][kqA]) = cvt4(a1n);
            *(float4*)(&Bs[nb][kB  ][nB4])   = cvt4(b0n);
            *(float4*)(&Bs[nb][kB+8][nB4])   = cvt4(b1n);
        }
        __syncthreads();
    }

    int valid = cnt - row0;
    #pragma unroll
    for (int mt = 0; mt < 2; mt++){
        int rbase = wm * 32 + mt * 16 + gq;
        #pragma unroll
        for (int half = 0; half < 2; half++){
            int m = rbase + half * 8;
            if (m < valid){
                size_t slot = (size_t)(off + row0 + m);
                #pragma unroll
                for (int nt = 0; nt < 8; nt++){
                    int c = n0 + wn * 64 + nt * 8 + qq * 2;
                    *(float2*)&g_Y[slot * HD + c] =
                        make_float2(acc[mt][nt][half*2+0], acc[mt][nt][half*2+1]);
                }
            }
        }
    }
}

// ---------------- K6: weighted combine ----------------
__global__ void k_combine(float* __restrict__ out){
    int t = blockIdx.x;
    float w0 = g_topw[2*t], w1 = g_topw[2*t+1];
    const float4* y0 = (const float4*)(g_Y + (size_t)g_slot[2*t]   * HD);
    const float4* y1 = (const float4*)(g_Y + (size_t)g_slot[2*t+1] * HD);
    float4* o = (float4*)(out + (size_t)t * HD);
    int i = threadIdx.x;
    float4 a = y0[i], b = y1[i];
    o[i] = make_float4(w0*a.x + w1*b.x, w0*a.y + w1*b.y,
                       w0*a.z + w1*b.z, w0*a.w + w1*b.w);
}

// ---------------- launch ----------------
extern "C" void kernel_launch(void* const* d_in, const int* in_sizes, int n_in,
                              void* d_out, int out_size){
    const float* x  = (const float*)d_in[0];
    const float* Wr = (const float*)d_in[1];
    const float* Wg = (const float*)d_in[2];
    const float* Wu = (const float*)d_in[3];
    const float* Wd = (const float*)d_in[4];
    float* out = (float*)d_out;

    cudaFuncSetAttribute(k_gateup, cudaFuncAttributeMaxDynamicSharedMemorySize,
                         GU_SMEM_FLOATS * 4);

    k_init<<<1, 32>>>();
    k_router<<<RB, 256>>>(x, Wr);
    k_finalize<<<1, 256>>>(out, out_size);
    k_assign<<<T_TOK / 256, 256>>>();

    dim3 g1(T_TOK / BM, ID / BN, NE);          // (64, 22, 8)
    k_gateup<<<g1, 256, GU_SMEM_FLOATS * 4>>>(x, Wg, Wu);
    dim3 g2(T_TOK / BM, HD / BN, NE);          // (64, 8, 8)
    k_down<<<g2, 256>>>(Wd);

    k_combine<<<T_TOK, 256>>>(out);
}

// round 9
// speedup vs baseline: 2.3811x; 1.3670x over previous
#include <cuda_runtime.h>
#include <math.h>
#include <stdint.h>

// Problem constants
#define T_TOK 8192
#define HD    1024
#define ID    2816
#define NE    8
#define NS    16384          // T_TOK * top_k
#define RB    1024

// GEMM tiling
#define BM 128
#define BN 128
#define BKT 16
#define ASTRIDE 20           // BKT+4 (A row pad, conflict-free frag loads)
#define BSTRIDE 136          // BN+8 -> mod 32 == 8 (conflict-free frag loads)
#define STAGES 4

// stage float layouts
#define GU_STG (2560+2176+2176)   // As + Bg + Bu = 6912 floats
#define DN_STG (2560+2176)        // As + Bs      = 4736 floats
#define GU_SMEM (STAGES*GU_STG*4) // 110592 B
#define DN_SMEM (STAGES*DN_STG*4) // 75776 B

// ---------------- scratch ----------------
__device__ float g_Hg [(size_t)NS*ID];      // silu(gate)*up, tf32-rounded
__device__ float g_Y  [(size_t)NS*HD];
__device__ float g_Xc [(size_t)T_TOK*HD];   // tf32(x)
__device__ float g_Wgc[(size_t)NE*HD*ID];   // tf32(Wg)
__device__ float g_Wuc[(size_t)NE*HD*ID];   // tf32(Wu)
__device__ float g_Wdc[(size_t)NE*ID*HD];   // tf32(Wd)
__device__ float g_topw[T_TOK*2];
__device__ int   g_topidx[T_TOK*2];
__device__ int   g_slot[T_TOK*2];
__device__ int   g_tok[NS];
__device__ int   g_cnt[NE];
__device__ int   g_off[NE];
__device__ int   g_fill[NE];
__device__ float g_probpart[RB*NE];

// ---------------- helpers ----------------
__device__ __forceinline__ unsigned f2tf(float x){
    unsigned r; asm("cvt.rna.tf32.f32 %0, %1;" : "=r"(r) : "f"(x)); return r;
}
__device__ __forceinline__ float4 cvt4(float4 v){
    float4 o;
    o.x = __uint_as_float(f2tf(v.x));
    o.y = __uint_as_float(f2tf(v.y));
    o.z = __uint_as_float(f2tf(v.z));
    o.w = __uint_as_float(f2tf(v.w));
    return o;
}
__device__ __forceinline__ void mma8(float* d, const unsigned* a, const unsigned* b){
    asm volatile(
        "mma.sync.aligned.m16n8k8.row.col.f32.tf32.tf32.f32 "
        "{%0,%1,%2,%3}, {%4,%5,%6,%7}, {%8,%9}, {%0,%1,%2,%3};\n"
        : "+f"(d[0]), "+f"(d[1]), "+f"(d[2]), "+f"(d[3])
        : "r"(a[0]), "r"(a[1]), "r"(a[2]), "r"(a[3]), "r"(b[0]), "r"(b[1]));
}
__device__ __forceinline__ uint32_t smem_u32(const void* p){
    uint32_t a;
    asm("{ .reg .u64 t; cvta.to.shared.u64 t, %1; cvt.u32.u64 %0, t; }" : "=r"(a) : "l"(p));
    return a;
}
__device__ __forceinline__ void cpa16(uint32_t d, const float* s){
    asm volatile("cp.async.cg.shared.global [%0], [%1], 16;" :: "r"(d), "l"(s) : "memory");
}
#define CP_COMMIT() asm volatile("cp.async.commit_group;" ::: "memory")
#define CP_WAIT2()  asm volatile("cp.async.wait_group 2;" ::: "memory")

// ---------------- K0: init ----------------
__global__ void k_init(){
    int i = threadIdx.x;
    if (i < NE){ g_cnt[i] = 0; g_fill[i] = 0; }
}

// ---------------- K: tf32 pre-convert (grid-stride float4) ----------------
__global__ void k_cvt(const float4* __restrict__ s, float4* __restrict__ d, int n4){
    int i = blockIdx.x * 256 + threadIdx.x;
    int st = gridDim.x * 256;
    for (; i < n4; i += st) d[i] = cvt4(s[i]);
}

// ---------------- K1: router ----------------
__global__ __launch_bounds__(256) void k_router(const float* __restrict__ x,
                                                const float* __restrict__ Wr){
    __shared__ float sp[8][8];
    __shared__ int   shc[8];
    int tid = threadIdx.x, wid = tid >> 5, lane = tid & 31;
    if (tid < 8) shc[tid] = 0;
    __syncthreads();

    int t = blockIdx.x * 8 + wid;
    const float* xr = x + (size_t)t * HD;
    float acc[8];
    #pragma unroll
    for (int e = 0; e < 8; e++) acc[e] = 0.f;

    for (int h0 = 0; h0 < HD; h0 += 32){
        float xv = xr[h0 + lane];
        const float4* w = (const float4*)(Wr + (size_t)(h0 + lane) * NE);
        float4 w0 = w[0], w1 = w[1];
        acc[0] += xv*w0.x; acc[1] += xv*w0.y; acc[2] += xv*w0.z; acc[3] += xv*w0.w;
        acc[4] += xv*w1.x; acc[5] += xv*w1.y; acc[6] += xv*w1.z; acc[7] += xv*w1.w;
    }
    #pragma unroll
    for (int e = 0; e < 8; e++)
        #pragma unroll
        for (int o = 16; o > 0; o >>= 1)
            acc[e] += __shfl_xor_sync(0xffffffffu, acc[e], o);

    if (lane == 0){
        float mx = acc[0];
        #pragma unroll
        for (int e = 1; e < 8; e++) mx = fmaxf(mx, acc[e]);
        float p[8], s = 0.f;
        #pragma unroll
        for (int e = 0; e < 8; e++){ p[e] = expf(acc[e] - mx); s += p[e]; }
        float inv = 1.f / s;
        #pragma unroll
        for (int e = 0; e < 8; e++){ p[e] *= inv; sp[wid][e] = p[e]; }
        int i0 = 0; float v0 = p[0];
        #pragma unroll
        for (int e = 1; e < 8; e++) if (p[e] > v0){ v0 = p[e]; i0 = e; }
        int i1 = -1; float v1 = -1.f;
        #pragma unroll
        for (int e = 0; e < 8; e++) if (e != i0 && p[e] > v1){ v1 = p[e]; i1 = e; }
        float rs = 1.f / (v0 + v1 + 1e-9f);
        g_topw[2*t]   = v0 * rs;  g_topw[2*t+1]   = v1 * rs;
        g_topidx[2*t] = i0;       g_topidx[2*t+1] = i1;
        atomicAdd(&shc[i0], 1);   atomicAdd(&shc[i1], 1);
    }
    __syncthreads();
    if (tid < 8){
        float s = 0.f;
        #pragma unroll
        for (int w = 0; w < 8; w++) s += sp[w][tid];
        g_probpart[blockIdx.x * 8 + tid] = s;
        atomicAdd(&g_cnt[tid], shc[tid]);
    }
}

// ---------------- K2: offsets + aux loss ----------------
__global__ void k_finalize(float* __restrict__ out, int out_size){
    __shared__ float sp2[32][8];
    __shared__ float pm[8];
    int tid = threadIdx.x;
    int e = tid & 7, ch = tid >> 3;
    float s = 0.f;
    for (int j = ch * 32; j < ch * 32 + 32; j++) s += g_probpart[j * 8 + e];
    sp2[ch][e] = s;
    __syncthreads();
    if (tid < 8){
        float ss = 0.f;
        for (int c = 0; c < 32; c++) ss += sp2[c][tid];
        pm[tid] = ss / (float)T_TOK;
        g_fill[tid] = 0;
    }
    __syncthreads();
    if (tid == 0){
        int o = 0;
        for (int i = 0; i < NE; i++){ g_off[i] = o; o += g_cnt[i]; }
        float loss = 0.f;
        for (int i = 0; i < NE; i++) loss += pm[i] * ((float)g_cnt[i] / (float)T_TOK);
        loss *= (float)NE * 0.01f;
        if (out_size > T_TOK * HD) out[T_TOK * HD] = loss;
    }
}

// ---------------- K3: slot assignment ----------------
__global__ void k_assign(){
    __shared__ int shc[8], shbase[8];
    int tid = threadIdx.x;
    int t = blockIdx.x * 256 + tid;
    if (tid < 8) shc[tid] = 0;
    __syncthreads();
    int e0 = g_topidx[2*t], e1 = g_topidx[2*t+1];
    int p0 = atomicAdd(&shc[e0], 1);
    int p1 = atomicAdd(&shc[e1], 1);
    __syncthreads();
    if (tid < 8) shbase[tid] = atomicAdd(&g_fill[tid], shc[tid]);
    __syncthreads();
    int s0 = g_off[e0] + shbase[e0] + p0;
    int s1 = g_off[e1] + shbase[e1] + p1;
    g_slot[2*t] = s0;  g_slot[2*t+1] = s1;
    g_tok[s0] = t;     g_tok[s1] = t;
}

// ---------------- K4: fused gate+up GEMM (cp.async 4-stage, 64x32 warp tiles) ----
__global__ __launch_bounds__(256, 1) void k_gateup(){
    extern __shared__ float smf[];
    uint32_t sm_u = smem_u32(smf);

    int e = blockIdx.z;
    int cnt = g_cnt[e], off = g_off[e];
    int row0 = blockIdx.x * BM;
    if (row0 >= cnt) return;
    int n0 = blockIdx.y * BN;
    const float* Wgp = g_Wgc + (size_t)e * HD * ID;
    const float* Wup = g_Wuc + (size_t)e * HD * ID;

    int tid = threadIdx.x, lane = tid & 31, wid = tid >> 5;
    int wm = wid & 1, wn = wid >> 1;           // 2x4 warps, warp tile 64x32
    int gq = lane >> 2, qq = lane & 3;

    // loaders
    int mA0 = tid >> 2, kqA = (tid & 3) * 4;   // A rows mA0, mA0+64
    int r0 = row0 + mA0, r1 = row0 + mA0 + 64;
    int t0 = (r0 < cnt) ? g_tok[off + r0] : 0;
    int t1 = (r1 < cnt) ? g_tok[off + r1] : 0;
    const float* arow0 = g_Xc + (size_t)t0 * HD + kqA;
    const float* arow1 = g_Xc + (size_t)t1 * HD + kqA;
    int kB = tid >> 5, nB4 = (tid & 31) * 4;   // B rows kB, kB+8
    const float* bgp = Wgp + (size_t)kB * ID + n0 + nB4;
    const float* bup = Wup + (size_t)kB * ID + n0 + nB4;

    uint32_t a0d = (uint32_t)((mA0*ASTRIDE + kqA) * 4);
    uint32_t a1d = (uint32_t)(((mA0+64)*ASTRIDE + kqA) * 4);
    uint32_t b0d = (uint32_t)(2560*4 + (kB*BSTRIDE + nB4) * 4);
    uint32_t b1d = b0d + 8*BSTRIDE*4;
    uint32_t u0d = b0d + 2176*4;
    uint32_t u1d = b1d + 2176*4;

    float accg[4][4][4], accu[4][4][4];
    #pragma unroll
    for (int mt = 0; mt < 4; mt++)
        #pragma unroll
        for (int nt = 0; nt < 4; nt++)
            #pragma unroll
            for (int i = 0; i < 4; i++){ accg[mt][nt][i] = 0.f; accu[mt][nt][i] = 0.f; }

    const int KT = HD / BKT;     // 64

    // prologue: stages 0..2
    #pragma unroll
    for (int p = 0; p < STAGES-1; p++){
        uint32_t sb = sm_u + (uint32_t)(p * GU_STG * 4);
        int ko = p * BKT;
        cpa16(sb + a0d, arow0 + ko);
        cpa16(sb + a1d, arow1 + ko);
        cpa16(sb + b0d, bgp + (size_t)ko * ID);
        cpa16(sb + b1d, bgp + (size_t)(ko+8) * ID);
        cpa16(sb + u0d, bup + (size_t)ko * ID);
        cpa16(sb + u1d, bup + (size_t)(ko+8) * ID);
        CP_COMMIT();
    }

    for (int kt = 0; kt < KT; kt++){
        CP_WAIT2();
        __syncthreads();
        int s = kt & (STAGES-1);
        const float* Asc = smf + s*GU_STG;
        const float* Bgc = Asc + 2560;
        const float* Buc = Asc + 4736;

        #pragma unroll
        for (int ks = 0; ks < 2; ks++){
            int k0 = ks * 8;
            unsigned af[4][4];
            #pragma unroll
            for (int mt = 0; mt < 4; mt++){
                int r = wm * 64 + mt * 16 + gq;
                af[mt][0] = __float_as_uint(Asc[(r    )*ASTRIDE + k0 + qq    ]);
                af[mt][1] = __float_as_uint(Asc[(r + 8)*ASTRIDE + k0 + qq    ]);
                af[mt][2] = __float_as_uint(Asc[(r    )*ASTRIDE + k0 + qq + 4]);
                af[mt][3] = __float_as_uint(Asc[(r + 8)*ASTRIDE + k0 + qq + 4]);
            }
            unsigned bfg[4][2], bfu[4][2];
            #pragma unroll
            for (int nt = 0; nt < 4; nt++){
                int c = wn * 32 + nt * 8 + gq;
                bfg[nt][0] = __float_as_uint(Bgc[(k0 + qq    )*BSTRIDE + c]);
                bfg[nt][1] = __float_as_uint(Bgc[(k0 + qq + 4)*BSTRIDE + c]);
                bfu[nt][0] = __float_as_uint(Buc[(k0 + qq    )*BSTRIDE + c]);
                bfu[nt][1] = __float_as_uint(Buc[(k0 + qq + 4)*BSTRIDE + c]);
            }
            #pragma unroll
            for (int mt = 0; mt < 4; mt++)
                #pragma unroll
                for (int nt = 0; nt < 4; nt++){
                    mma8(accg[mt][nt], af[mt], bfg[nt]);
                    mma8(accu[mt][nt], af[mt], bfu[nt]);
                }
        }

        int kp = kt + STAGES - 1;
        if (kp < KT){
            uint32_t sb = sm_u + (uint32_t)((kp & (STAGES-1)) * GU_STG * 4);
            int ko = kp * BKT;
            cpa16(sb + a0d, arow0 + ko);
            cpa16(sb + a1d, arow1 + ko);
            cpa16(sb + b0d, bgp + (size_t)ko * ID);
            cpa16(sb + b1d, bgp + (size_t)(ko+8) * ID);
            cpa16(sb + u0d, bup + (size_t)ko * ID);
            cpa16(sb + u1d, bup + (size_t)(ko+8) * ID);
        }
        CP_COMMIT();
    }

    // epilogue: silu(g)*u, tf32-rounded -> g_Hg
    int valid = cnt - row0;
    #pragma unroll
    for (int mt = 0; mt < 4; mt++){
        #pragma unroll
        for (int half = 0; half < 2; half++){
            int m = wm * 64 + mt * 16 + half * 8 + gq;
            if (m < valid){
                size_t slot = (size_t)(off + row0 + m);
                #pragma unroll
                for (int nt = 0; nt < 4; nt++){
                    int c = n0 + wn * 32 + nt * 8 + qq * 2;
                    float gg0 = accg[mt][nt][half * 2 + 0];
                    float gg1 = accg[mt][nt][half * 2 + 1];
                    float uu0 = accu[mt][nt][half * 2 + 0];
                    float uu1 = accu[mt][nt][half * 2 + 1];
                    float h0 = gg0 / (1.f + expf(-gg0)) * uu0;
                    float h1 = gg1 / (1.f + expf(-gg1)) * uu1;
                    float2 hv;
                    hv.x = __uint_as_float(f2tf(h0));
                    hv.y = __uint_as_float(f2tf(h1));
                    *(float2*)&g_Hg[slot * ID + c] = hv;
                }
            }
        }
    }
}

// ---------------- K5: down GEMM (cp.async 4-stage, 64x32 warp tiles) ----------
__global__ __launch_bounds__(256, 2) void k_down(){
    extern __shared__ float smf[];
    uint32_t sm_u = smem_u32(smf);

    int e = blockIdx.z;
    int cnt = g_cnt[e], off = g_off[e];
    int row0 = blockIdx.x * BM;
    if (row0 >= cnt) return;
    int n0 = blockIdx.y * BN;
    const float* Wp = g_Wdc + (size_t)e * ID * HD;

    int tid = threadIdx.x, lane = tid & 31, wid = tid >> 5;
    int wm = wid & 1, wn = wid >> 1;
    int gq = lane >> 2, qq = lane & 3;

    int mA0 = tid >> 2, kqA = (tid & 3) * 4;
    int s0 = off + row0 + mA0;      if (s0 >= NS) s0 = NS - 1;
    int s1 = off + row0 + mA0 + 64; if (s1 >= NS) s1 = NS - 1;
    const float* arow0 = g_Hg + (size_t)s0 * ID + kqA;
    const float* arow1 = g_Hg + (size_t)s1 * ID + kqA;
    int kB = tid >> 5, nB4 = (tid & 31) * 4;
    const float* bptr = Wp + (size_t)kB * HD + n0 + nB4;

    uint32_t a0d = (uint32_t)((mA0*ASTRIDE + kqA) * 4);
    uint32_t a1d = (uint32_t)(((mA0+64)*ASTRIDE + kqA) * 4);
    uint32_t b0d = (uint32_t)(2560*4 + (kB*BSTRIDE + nB4) * 4);
    uint32_t b1d = b0d + 8*BSTRIDE*4;

    float acc[4][4][4];
    #pragma unroll
    for (int mt = 0; mt < 4; mt++)
        #pragma unroll
        for (int nt = 0; nt < 4; nt++)
            #pragma unroll
            for (int i = 0; i < 4; i++) acc[mt][nt][i] = 0.f;

    const int KT = ID / BKT;      // 176

    #pragma unroll
    for (int p = 0; p < STAGES-1; p++){
        uint32_t sb = sm_u + (uint32_t)(p * DN_STG * 4);
        int ko = p * BKT;
        cpa16(sb + a0d, arow0 + ko);
        cpa16(sb + a1d, arow1 + ko);
        cpa16(sb + b0d, bptr + (size_t)ko * HD);
        cpa16(sb + b1d, bptr + (size_t)(ko+8) * HD);
        CP_COMMIT();
    }

    for (int kt = 0; kt < KT; kt++){
        CP_WAIT2();
        __syncthreads();
        int s = kt & (STAGES-1);
        const float* Asc = smf + s*DN_STG;
        const float* Bsc = Asc + 2560;

        #pragma unroll
        for (int ks = 0; ks < 2; ks++){
            int k0 = ks * 8;
            unsigned af[4][4];
            #pragma unroll
            for (int mt = 0; mt < 4; mt++){
                int r = wm * 64 + mt * 16 + gq;
                af[mt][0] = __float_as_uint(Asc[(r    )*ASTRIDE + k0 + qq    ]);
                af[mt][1] = __float_as_uint(Asc[(r + 8)*ASTRIDE + k0 + qq    ]);
                af[mt][2] = __float_as_uint(Asc[(r    )*ASTRIDE + k0 + qq + 4]);
                af[mt][3] = __float_as_uint(Asc[(r + 8)*ASTRIDE + k0 + qq + 4]);
            }
            unsigned bf[4][2];
            #pragma unroll
            for (int nt = 0; nt < 4; nt++){
                int c = wn * 32 + nt * 8 + gq;
                bf[nt][0] = __float_as_uint(Bsc[(k0 + qq    )*BSTRIDE + c]);
                bf[nt][1] = __float_as_uint(Bsc[(k0 + qq + 4)*BSTRIDE + c]);
            }
            #pragma unroll
            for (int mt = 0; mt < 4; mt++)
                #pragma unroll
                for (int nt = 0; nt < 4; nt++)
                    mma8(acc[mt][nt], af[mt], bf[nt]);
        }

        int kp = kt + STAGES - 1;
        if (kp < KT){
            uint32_t sb = sm_u + (uint32_t)((kp & (STAGES-1)) * DN_STG * 4);
            int ko = kp * BKT;
            cpa16(sb + a0d, arow0 + ko);
            cpa16(sb + a1d, arow1 + ko);
            cpa16(sb + b0d, bptr + (size_t)ko * HD);
            cpa16(sb + b1d, bptr + (size_t)(ko+8) * HD);
        }
        CP_COMMIT();
    }

    int valid = cnt - row0;
    #pragma unroll
    for (int mt = 0; mt < 4; mt++){
        #pragma unroll
        for (int half = 0; half < 2; half++){
            int m = wm * 64 + mt * 16 + half * 8 + gq;
            if (m < valid){
                size_t slot = (size_t)(off + row0 + m);
                #pragma unroll
                for (int nt = 0; nt < 4; nt++){
                    int c = n0 + wn * 32 + nt * 8 + qq * 2;
                    *(float2*)&g_Y[slot * HD + c] =
                        make_float2(acc[mt][nt][half*2+0], acc[mt][nt][half*2+1]);
                }
            }
        }
    }
}

// ---------------- K6: weighted combine ----------------
__global__ void k_combine(float* __restrict__ out){
    int t = blockIdx.x;
    float w0 = g_topw[2*t], w1 = g_topw[2*t+1];
    const float4* y0 = (const float4*)(g_Y + (size_t)g_slot[2*t]   * HD);
    const float4* y1 = (const float4*)(g_Y + (size_t)g_slot[2*t+1] * HD);
    float4* o = (float4*)(out + (size_t)t * HD);
    int i = threadIdx.x;
    float4 a = y0[i], b = y1[i];
    o[i] = make_float4(w0*a.x + w1*b.x, w0*a.y + w1*b.y,
                       w0*a.z + w1*b.z, w0*a.w + w1*b.w);
}

// ---------------- launch ----------------
extern "C" void kernel_launch(void* const* d_in, const int* in_sizes, int n_in,
                              void* d_out, int out_size){
    const float* x  = (const float*)d_in[0];
    const float* Wr = (const float*)d_in[1];
    const float* Wg = (const float*)d_in[2];
    const float* Wu = (const float*)d_in[3];
    const float* Wd = (const float*)d_in[4];
    float* out = (float*)d_out;

    float *xc, *wgc, *wuc, *wdc;
    cudaGetSymbolAddress((void**)&xc,  g_Xc);
    cudaGetSymbolAddress((void**)&wgc, g_Wgc);
    cudaGetSymbolAddress((void**)&wuc, g_Wuc);
    cudaGetSymbolAddress((void**)&wdc, g_Wdc);

    cudaFuncSetAttribute(k_gateup, cudaFuncAttributeMaxDynamicSharedMemorySize, GU_SMEM);
    cudaFuncSetAttribute(k_down,   cudaFuncAttributeMaxDynamicSharedMemorySize, DN_SMEM);

    k_init<<<1, 32>>>();
    int nW4 = NE * HD * ID / 4;                // 5,767,168
    int nX4 = T_TOK * HD / 4;                  // 2,097,152
    k_cvt<<<4096, 256>>>((const float4*)x,  (float4*)xc,  nX4);
    k_cvt<<<4096, 256>>>((const float4*)Wg, (float4*)wgc, nW4);
    k_cvt<<<4096, 256>>>((const float4*)Wu, (float4*)wuc, nW4);
    k_cvt<<<4096, 256>>>((const float4*)Wd, (float4*)wdc, nW4);

    k_router<<<RB, 256>>>(x, Wr);
    k_finalize<<<1, 256>>>(out, out_size);
    k_assign<<<T_TOK / 256, 256>>>();

    dim3 g1(T_TOK / BM, ID / BN, NE);          // (64, 22, 8)
    k_gateup<<<g1, 256, GU_SMEM>>>();
    dim3 g2(T_TOK / BM, HD / BN, NE);          // (64, 8, 8)
    k_down<<<g2, 256, DN_SMEM>>>();

    k_combine<<<T_TOK, 256>>>(out);
}

// round 10
// speedup vs baseline: 2.4933x; 1.0471x over previous
#include <cuda_runtime.h>
#include <math.h>
#include <stdint.h>

// Problem constants
#define T_TOK 8192
#define HD    1024
#define ID    2816
#define NE    8
#define NS    16384          // T_TOK * top_k
#define RB    1024

// GEMM tiling
#define BN 128
#define BKT 32
#define ASTRIDE 36           // BKT+4 (mod 32 == 4 -> conflict-free A frags)
#define BSTRIDE 136          // BN+8  (mod 32 == 8 -> conflict-free B frags)
#define STAGES 3

// gateup: BM=128. stage floats: A 128*36=4608, Bg 4352, Bu 4352
#define GU_BM   128
#define GU_AS   4608
#define GU_BG   4352
#define GU_STG  (GU_AS + 2*GU_BG)          // 13312
#define GU_SMEM (STAGES*GU_STG*4)          // 159744 B

// down: BM=256. stage floats: A 256*36=9216, Bs 4352
#define DN_BM   256
#define DN_AS   9216
#define DN_STG  (DN_AS + 4352)             // 13568
#define DN_SMEM (STAGES*DN_STG*4)          // 162816 B

// ---------------- scratch ----------------
__device__ float g_Hg [(size_t)NS*ID];      // silu(gate)*up, tf32-rounded
__device__ float g_Y  [(size_t)NS*HD];
__device__ float g_Xc [(size_t)T_TOK*HD];   // tf32(x)
__device__ float g_Wgc[(size_t)NE*HD*ID];
__device__ float g_Wuc[(size_t)NE*HD*ID];
__device__ float g_Wdc[(size_t)NE*ID*HD];
__device__ float g_topw[T_TOK*2];
__device__ int   g_topidx[T_TOK*2];
__device__ int   g_slot[T_TOK*2];
__device__ int   g_tok[NS];
__device__ int   g_cnt[NE];
__device__ int   g_off[NE];
__device__ int   g_fill[NE];
__device__ float g_probpart[RB*NE];

// ---------------- helpers ----------------
__device__ __forceinline__ unsigned f2tf(float x){
    unsigned r; asm("cvt.rna.tf32.f32 %0, %1;" : "=r"(r) : "f"(x)); return r;
}
__device__ __forceinline__ float4 cvt4(float4 v){
    float4 o;
    o.x = __uint_as_float(f2tf(v.x));
    o.y = __uint_as_float(f2tf(v.y));
    o.z = __uint_as_float(f2tf(v.z));
    o.w = __uint_as_float(f2tf(v.w));
    return o;
}
__device__ __forceinline__ void mma8(float* d, const unsigned* a, const unsigned* b){
    asm volatile(
        "mma.sync.aligned.m16n8k8.row.col.f32.tf32.tf32.f32 "
        "{%0,%1,%2,%3}, {%4,%5,%6,%7}, {%8,%9}, {%0,%1,%2,%3};\n"
        : "+f"(d[0]), "+f"(d[1]), "+f"(d[2]), "+f"(d[3])
        : "r"(a[0]), "r"(a[1]), "r"(a[2]), "r"(a[3]), "r"(b[0]), "r"(b[1]));
}
__device__ __forceinline__ uint32_t smem_u32(const void* p){
    uint32_t a;
    asm("{ .reg .u64 t; cvta.to.shared.u64 t, %1; cvt.u32.u64 %0, t; }" : "=r"(a) : "l"(p));
    return a;
}
__device__ __forceinline__ void cpa16(uint32_t d, const float* s){
    asm volatile("cp.async.cg.shared.global [%0], [%1], 16;" :: "r"(d), "l"(s) : "memory");
}
#define CP_COMMIT() asm volatile("cp.async.commit_group;" ::: "memory")
#define CP_WAIT1()  asm volatile("cp.async.wait_group 1;" ::: "memory")

// ---------------- K0: init ----------------
__global__ void k_init(){
    int i = threadIdx.x;
    if (i < NE){ g_cnt[i] = 0; g_fill[i] = 0; }
}

// ---------------- K: merged tf32 pre-convert ----------------
__global__ void k_cvt_all(const float4* __restrict__ x,  float4* __restrict__ xc,
                          const float4* __restrict__ wg, float4* __restrict__ wgc,
                          const float4* __restrict__ wu, float4* __restrict__ wuc,
                          const float4* __restrict__ wd, float4* __restrict__ wdc){
    const long nX4 = (long)T_TOK*HD/4;
    const long nW4 = (long)NE*HD*ID/4;
    const long total = nX4 + 3*nW4;
    long st = (long)gridDim.x * 256;
    for (long i = (long)blockIdx.x*256 + threadIdx.x; i < total; i += st){
        if (i < nX4){ xc[i] = cvt4(x[i]); }
        else {
            long j = i - nX4;
            if (j < nW4)            wgc[j]       = cvt4(wg[j]);
            else if (j < 2*nW4)     wuc[j-nW4]   = cvt4(wu[j-nW4]);
            else                    wdc[j-2*nW4] = cvt4(wd[j-2*nW4]);
        }
    }
}

// ---------------- K1: router ----------------
__global__ __launch_bounds__(256) void k_router(const float* __restrict__ x,
                                                const float* __restrict__ Wr){
    __shared__ float sp[8][8];
    __shared__ int   shc[8];
    int tid = threadIdx.x, wid = tid >> 5, lane = tid & 31;
    if (tid < 8) shc[tid] = 0;
    __syncthreads();

    int t = blockIdx.x * 8 + wid;
    const float* xr = x + (size_t)t * HD;
    float acc[8];
    #pragma unroll
    for (int e = 0; e < 8; e++) acc[e] = 0.f;

    for (int h0 = 0; h0 < HD; h0 += 32){
        float xv = xr[h0 + lane];
        const float4* w = (const float4*)(Wr + (size_t)(h0 + lane) * NE);
        float4 w0 = w[0], w1 = w[1];
        acc[0] += xv*w0.x; acc[1] += xv*w0.y; acc[2] += xv*w0.z; acc[3] += xv*w0.w;
        acc[4] += xv*w1.x; acc[5] += xv*w1.y; acc[6] += xv*w1.z; acc[7] += xv*w1.w;
    }
    #pragma unroll
    for (int e = 0; e < 8; e++)
        #pragma unroll
        for (int o = 16; o > 0; o >>= 1)
            acc[e] += __shfl_xor_sync(0xffffffffu, acc[e], o);

    if (lane == 0){
        float mx = acc[0];
        #pragma unroll
        for (int e = 1; e < 8; e++) mx = fmaxf(mx, acc[e]);
        float p[8], s = 0.f;
        #pragma unroll
        for (int e = 0; e < 8; e++){ p[e] = expf(acc[e] - mx); s += p[e]; }
        float inv = 1.f / s;
        #pragma unroll
        for (int e = 0; e < 8; e++){ p[e] *= inv; sp[wid][e] = p[e]; }
        int i0 = 0; float v0 = p[0];
        #pragma unroll
        for (int e = 1; e < 8; e++) if (p[e] > v0){ v0 = p[e]; i0 = e; }
        int i1 = -1; float v1 = -1.f;
        #pragma unroll
        for (int e = 0; e < 8; e++) if (e != i0 && p[e] > v1){ v1 = p[e]; i1 = e; }
        float rs = 1.f / (v0 + v1 + 1e-9f);
        g_topw[2*t]   = v0 * rs;  g_topw[2*t+1]   = v1 * rs;
        g_topidx[2*t] = i0;       g_topidx[2*t+1] = i1;
        atomicAdd(&shc[i0], 1);   atomicAdd(&shc[i1], 1);
    }
    __syncthreads();
    if (tid < 8){
        float s = 0.f;
        #pragma unroll
        for (int w = 0; w < 8; w++) s += sp[w][tid];
        g_probpart[blockIdx.x * 8 + tid] = s;
        atomicAdd(&g_cnt[tid], shc[tid]);
    }
}

// ---------------- K2: offsets + aux loss ----------------
__global__ void k_finalize(float* __restrict__ out, int out_size){
    __shared__ float sp2[32][8];
    __shared__ float pm[8];
    int tid = threadIdx.x;
    int e = tid & 7, ch = tid >> 3;
    float s = 0.f;
    for (int j = ch * 32; j < ch * 32 + 32; j++) s += g_probpart[j * 8 + e];
    sp2[ch][e] = s;
    __syncthreads();
    if (tid < 8){
        float ss = 0.f;
        for (int c = 0; c < 32; c++) ss += sp2[c][tid];
        pm[tid] = ss / (float)T_TOK;
        g_fill[tid] = 0;
    }
    __syncthreads();
    if (tid == 0){
        int o = 0;
        for (int i = 0; i < NE; i++){ g_off[i] = o; o += g_cnt[i]; }
        float loss = 0.f;
        for (int i = 0; i < NE; i++) loss += pm[i] * ((float)g_cnt[i] / (float)T_TOK);
        loss *= (float)NE * 0.01f;
        if (out_size > T_TOK * HD) out[T_TOK * HD] = loss;
    }
}

// ---------------- K3: slot assignment ----------------
__global__ void k_assign(){
    __shared__ int shc[8], shbase[8];
    int tid = threadIdx.x;
    int t = blockIdx.x * 256 + tid;
    if (tid < 8) shc[tid] = 0;
    __syncthreads();
    int e0 = g_topidx[2*t], e1 = g_topidx[2*t+1];
    int p0 = atomicAdd(&shc[e0], 1);
    int p1 = atomicAdd(&shc[e1], 1);
    __syncthreads();
    if (tid < 8) shbase[tid] = atomicAdd(&g_fill[tid], shc[tid]);
    __syncthreads();
    int s0 = g_off[e0] + shbase[e0] + p0;
    int s1 = g_off[e1] + shbase[e1] + p1;
    g_slot[2*t] = s0;  g_slot[2*t+1] = s1;
    g_tok[s0] = t;     g_tok[s1] = t;
}

// ---------------- K4: fused gate+up GEMM (BKT32, 3-stage cp.async) ----------
__global__ __launch_bounds__(256, 1) void k_gateup(){
    extern __shared__ float smf[];
    uint32_t sm_u = smem_u32(smf);

    int e = blockIdx.z;
    int cnt = g_cnt[e], off = g_off[e];
    int row0 = blockIdx.x * GU_BM;
    if (row0 >= cnt) return;
    int n0 = blockIdx.y * BN;
    const float* Wgp = g_Wgc + (size_t)e * HD * ID;
    const float* Wup = g_Wuc + (size_t)e * HD * ID;

    int tid = threadIdx.x, lane = tid & 31, wid = tid >> 5;
    int wm = wid & 1, wn = wid >> 1;           // 2x4 warps, warp tile 64x32
    int gq = lane >> 2, qq = lane & 3;

    // A loader: 4 rows/thread, rows mA+32i, cols kq..kq+3
    int mA = tid >> 3, kq = (tid & 7) * 4;
    const float* arow[4];
    uint32_t adst[4];
    #pragma unroll
    for (int i = 0; i < 4; i++){
        int rl = mA + 32*i;
        int r = row0 + rl;
        int t = (r < cnt) ? g_tok[off + r] : 0;
        arow[i] = g_Xc + (size_t)t * HD + kq;
        adst[i] = (uint32_t)((rl*ASTRIDE + kq) * 4);
    }
    // B loaders: 4 k-rows/thread per matrix
    int kB = tid >> 5, nB4 = (tid & 31) * 4;
    const float* bgp = Wgp + (size_t)kB * ID + n0 + nB4;
    const float* bup = Wup + (size_t)kB * ID + n0 + nB4;
    uint32_t bdst[4];
    #pragma unroll
    for (int i = 0; i < 4; i++)
        bdst[i] = (uint32_t)(GU_AS*4 + ((kB + 8*i)*BSTRIDE + nB4) * 4);

    float accg[4][4][4], accu[4][4][4];
    #pragma unroll
    for (int mt = 0; mt < 4; mt++)
        #pragma unroll
        for (int nt = 0; nt < 4; nt++)
            #pragma unroll
            for (int i = 0; i < 4; i++){ accg[mt][nt][i] = 0.f; accu[mt][nt][i] = 0.f; }

    const int KT = HD / BKT;     // 32

    #pragma unroll
    for (int p = 0; p < STAGES-1; p++){
        uint32_t sb = sm_u + (uint32_t)(p * GU_STG * 4);
        int ko = p * BKT;
        #pragma unroll
        for (int i = 0; i < 4; i++) cpa16(sb + adst[i], arow[i] + ko);
        #pragma unroll
        for (int i = 0; i < 4; i++) cpa16(sb + bdst[i], bgp + (size_t)(ko + 8*i) * ID);
        #pragma unroll
        for (int i = 0; i < 4; i++) cpa16(sb + bdst[i] + GU_BG*4, bup + (size_t)(ko + 8*i) * ID);
        CP_COMMIT();
    }

    for (int kt = 0; kt < KT; kt++){
        CP_WAIT1();
        __syncthreads();
        int s = kt % STAGES;
        const float* Asc = smf + s*GU_STG;
        const float* Bgc = Asc + GU_AS;
        const float* Buc = Bgc + GU_BG;

        #pragma unroll
        for (int ks = 0; ks < 4; ks++){
            int k0 = ks * 8;
            unsigned af[4][4];
            #pragma unroll
            for (int mt = 0; mt < 4; mt++){
                int r = wm * 64 + mt * 16 + gq;
                af[mt][0] = __float_as_uint(Asc[(r    )*ASTRIDE + k0 + qq    ]);
                af[mt][1] = __float_as_uint(Asc[(r + 8)*ASTRIDE + k0 + qq    ]);
                af[mt][2] = __float_as_uint(Asc[(r    )*ASTRIDE + k0 + qq + 4]);
                af[mt][3] = __float_as_uint(Asc[(r + 8)*ASTRIDE + k0 + qq + 4]);
            }
            unsigned bfg[4][2], bfu[4][2];
            #pragma unroll
            for (int nt = 0; nt < 4; nt++){
                int c = wn * 32 + nt * 8 + gq;
                bfg[nt][0] = __float_as_uint(Bgc[(k0 + qq    )*BSTRIDE + c]);
                bfg[nt][1] = __float_as_uint(Bgc[(k0 + qq + 4)*BSTRIDE + c]);
                bfu[nt][0] = __float_as_uint(Buc[(k0 + qq    )*BSTRIDE + c]);
                bfu[nt][1] = __float_as_uint(Buc[(k0 + qq + 4)*BSTRIDE + c]);
            }
            #pragma unroll
            for (int mt = 0; mt < 4; mt++)
                #pragma unroll
                for (int nt = 0; nt < 4; nt++){
                    mma8(accg[mt][nt], af[mt], bfg[nt]);
                    mma8(accu[mt][nt], af[mt], bfu[nt]);
                }
        }

        int kp = kt + STAGES - 1;
        if (kp < KT){
            uint32_t sb = sm_u + (uint32_t)((kp % STAGES) * GU_STG * 4);
            int ko = kp * BKT;
            #pragma unroll
            for (int i = 0; i < 4; i++) cpa16(sb + adst[i], arow[i] + ko);
            #pragma unroll
            for (int i = 0; i < 4; i++) cpa16(sb + bdst[i], bgp + (size_t)(ko + 8*i) * ID);
            #pragma unroll
            for (int i = 0; i < 4; i++) cpa16(sb + bdst[i] + GU_BG*4, bup + (size_t)(ko + 8*i) * ID);
        }
        CP_COMMIT();
    }

    // epilogue: silu(g)*u, tf32-rounded -> g_Hg
    int valid = cnt - row0;
    #pragma unroll
    for (int mt = 0; mt < 4; mt++){
        #pragma unroll
        for (int half = 0; half < 2; half++){
            int m = wm * 64 + mt * 16 + half * 8 + gq;
            if (m < valid){
                size_t slot = (size_t)(off + row0 + m);
                #pragma unroll
                for (int nt = 0; nt < 4; nt++){
                    int c = n0 + wn * 32 + nt * 8 + qq * 2;
                    float gg0 = accg[mt][nt][half * 2 + 0];
                    float gg1 = accg[mt][nt][half * 2 + 1];
                    float uu0 = accu[mt][nt][half * 2 + 0];
                    float uu1 = accu[mt][nt][half * 2 + 1];
                    float h0 = gg0 / (1.f + expf(-gg0)) * uu0;
                    float h1 = gg1 / (1.f + expf(-gg1)) * uu1;
                    float2 hv;
                    hv.x = __uint_as_float(f2tf(h0));
                    hv.y = __uint_as_float(f2tf(h1));
                    *(float2*)&g_Hg[slot * ID + c] = hv;
                }
            }
        }
    }
}

// ---------------- K5: down GEMM (BM=256, 64x64 warp tiles, BKT32) ----------
__global__ __launch_bounds__(256, 1) void k_down(){
    extern __shared__ float smf[];
    uint32_t sm_u = smem_u32(smf);

    int e = blockIdx.z;
    int cnt = g_cnt[e], off = g_off[e];
    int row0 = blockIdx.x * DN_BM;
    if (row0 >= cnt) return;
    int n0 = blockIdx.y * BN;
    const float* Wp = g_Wdc + (size_t)e * ID * HD;

    int tid = threadIdx.x, lane = tid & 31, wid = tid >> 5;
    int wm = wid & 3, wn = wid >> 2;           // 4x2 warps, warp tile 64x64
    int gq = lane >> 2, qq = lane & 3;

    // A loader: 8 rows/thread
    int mA = tid >> 3, kq = (tid & 7) * 4;
    const float* arow[8];
    uint32_t adst[8];
    #pragma unroll
    for (int i = 0; i < 8; i++){
        int rl = mA + 32*i;
        int s = off + row0 + rl; if (s >= NS) s = NS - 1;
        arow[i] = g_Hg + (size_t)s * ID + kq;
        adst[i] = (uint32_t)((rl*ASTRIDE + kq) * 4);
    }
    int kB = tid >> 5, nB4 = (tid & 31) * 4;
    const float* bptr = Wp + (size_t)kB * HD + n0 + nB4;
    uint32_t bdst[4];
    #pragma unroll
    for (int i = 0; i < 4; i++)
        bdst[i] = (uint32_t)(DN_AS*4 + ((kB + 8*i)*BSTRIDE + nB4) * 4);

    float acc[4][8][4];
    #pragma unroll
    for (int mt = 0; mt < 4; mt++)
        #pragma unroll
        for (int nt = 0; nt < 8; nt++)
            #pragma unroll
            for (int i = 0; i < 4; i++) acc[mt][nt][i] = 0.f;

    const int KT = ID / BKT;      // 88

    #pragma unroll
    for (int p = 0; p < STAGES-1; p++){
        uint32_t sb = sm_u + (uint32_t)(p * DN_STG * 4);
        int ko = p * BKT;
        #pragma unroll
        for (int i = 0; i < 8; i++) cpa16(sb + adst[i], arow[i] + ko);
        #pragma unroll
        for (int i = 0; i < 4; i++) cpa16(sb + bdst[i], bptr + (size_t)(ko + 8*i) * HD);
        CP_COMMIT();
    }

    for (int kt = 0; kt < KT; kt++){
        CP_WAIT1();
        __syncthreads();
        int s = kt % STAGES;
        const float* Asc = smf + s*DN_STG;
        const float* Bsc = Asc + DN_AS;

        #pragma unroll
        for (int ks = 0; ks < 4; ks++){
            int k0 = ks * 8;
            unsigned af[4][4];
            #pragma unroll
            for (int mt = 0; mt < 4; mt++){
                int r = wm * 64 + mt * 16 + gq;
                af[mt][0] = __float_as_uint(Asc[(r    )*ASTRIDE + k0 + qq    ]);
                af[mt][1] = __float_as_uint(Asc[(r + 8)*ASTRIDE + k0 + qq    ]);
                af[mt][2] = __float_as_uint(Asc[(r    )*ASTRIDE + k0 + qq + 4]);
                af[mt][3] = __float_as_uint(Asc[(r + 8)*ASTRIDE + k0 + qq + 4]);
            }
            unsigned bf[8][2];
            #pragma unroll
            for (int nt = 0; nt < 8; nt++){
                int c = wn * 64 + nt * 8 + gq;
                bf[nt][0] = __float_as_uint(Bsc[(k0 + qq    )*BSTRIDE + c]);
                bf[nt][1] = __float_as_uint(Bsc[(k0 + qq + 4)*BSTRIDE + c]);
            }
            #pragma unroll
            for (int mt = 0; mt < 4; mt++)
                #pragma unroll
                for (int nt = 0; nt < 8; nt++)
                    mma8(acc[mt][nt], af[mt], bf[nt]);
        }

        int kp = kt + STAGES - 1;
        if (kp < KT){
            uint32_t sb = sm_u + (uint32_t)((kp % STAGES) * DN_STG * 4);
            int ko = kp * BKT;
            #pragma unroll
            for (int i = 0; i < 8; i++) cpa16(sb + adst[i], arow[i] + ko);
            #pragma unroll
            for (int i = 0; i < 4; i++) cpa16(sb + bdst[i], bptr + (size_t)(ko + 8*i) * HD);
        }
        CP_COMMIT();
    }

    int valid = cnt - row0;
    #pragma unroll
    for (int mt = 0; mt < 4; mt++){
        #pragma unroll
        for (int half = 0; half < 2; half++){
            int m = wm * 64 + mt * 16 + half * 8 + gq;
            if (m < valid){
                size_t slot = (size_t)(off + row0 + m);
                #pragma unroll
                for (int nt = 0; nt < 8; nt++){
                    int c = n0 + wn * 64 + nt * 8 + qq * 2;
                    *(float2*)&g_Y[slot * HD + c] =
                        make_float2(acc[mt][nt][half*2+0], acc[mt][nt][half*2+1]);
                }
            }
        }
    }
}

// ---------------- K6: weighted combine ----------------
__global__ void k_combine(float* __restrict__ out){
    int t = blockIdx.x;
    float w0 = g_topw[2*t], w1 = g_topw[2*t+1];
    const float4* y0 = (const float4*)(g_Y + (size_t)g_slot[2*t]   * HD);
    const float4* y1 = (const float4*)(g_Y + (size_t)g_slot[2*t+1] * HD);
    float4* o = (float4*)(out + (size_t)t * HD);
    int i = threadIdx.x;
    float4 a = y0[i], b = y1[i];
    o[i] = make_float4(w0*a.x + w1*b.x, w0*a.y + w1*b.y,
                       w0*a.z + w1*b.z, w0*a.w + w1*b.w);
}

// ---------------- launch ----------------
extern "C" void kernel_launch(void* const* d_in, const int* in_sizes, int n_in,
                              void* d_out, int out_size){
    const float* x  = (const float*)d_in[0];
    const float* Wr = (const float*)d_in[1];
    const float* Wg = (const float*)d_in[2];
    const float* Wu = (const float*)d_in[3];
    const float* Wd = (const float*)d_in[4];
    float* out = (float*)d_out;

    float *xc, *wgc, *wuc, *wdc;
    cudaGetSymbolAddress((void**)&xc,  g_Xc);
    cudaGetSymbolAddress((void**)&wgc, g_Wgc);
    cudaGetSymbolAddress((void**)&wuc, g_Wuc);
    cudaGetSymbolAddress((void**)&wdc, g_Wdc);

    cudaFuncSetAttribute(k_gateup, cudaFuncAttributeMaxDynamicSharedMemorySize, GU_SMEM);
    cudaFuncSetAttribute(k_down,   cudaFuncAttributeMaxDynamicSharedMemorySize, DN_SMEM);

    k_init<<<1, 32>>>();
    k_cvt_all<<<8192, 256>>>((const float4*)x,  (float4*)xc,
                             (const float4*)Wg, (float4*)wgc,
                             (const float4*)Wu, (float4*)wuc,
                             (const float4*)Wd, (float4*)wdc);
    k_router<<<RB, 256>>>(x, Wr);
    k_finalize<<<1, 256>>>(out, out_size);
    k_assign<<<T_TOK / 256, 256>>>();

    dim3 g1(T_TOK / GU_BM, ID / BN, NE);       // (64, 22, 8)
    k_gateup<<<g1, 256, GU_SMEM>>>();
    dim3 g2(T_TOK / DN_BM, HD / BN, NE);       // (32, 8, 8)
    k_down<<<g2, 256, DN_SMEM>>>();

    k_combine<<<T_TOK, 256>>>(out);
}